// round 13
// baseline (speedup 1.0000x reference)
#include <cuda_runtime.h>
#include <cuda_fp16.h>

// Vanilla tanh RNN: B=4096, T=2048, I=4, H=20, O=4.
// R13: 4 lanes per batch -> 8 batches/warp, ALL 32 lanes live. Each lane owns
// outputs {5r..5r+4}. h stored per batch as 10 fp16x2 words in a custom pairing:
//   w_{2r}   = {h_{5r},   h_{5r+1}}     w_{2r+1} = {h_{5r+2}, h_{5r+3}}   (r=0..3)
//   w8 = {h4, h9}   w9 = {h14, h19}    (each lane's 5th output, half-word store)
// W_hh is packed at init following the same pairing, so the dot is 10 HFMA2 per
// output with zero repacking. 4 warps/CTA (1/SMSP), grid 128: 128*4*8 = 4096
// exactly -- no dead lanes, no clamping. Warp-private SMEM ping-pong exchange,
// syncwarp-free (in-order per-warp LSU + compiler fence), tanh.approx.f16x2,
// 8-deep fp32 x register prefetch ring.

#define B_TOTAL 4096
#define T_STEPS 2048
#define H_DIM   20
#define WARPS_CTA 4
#define CTA_THREADS (WARPS_CTA * 32)
#define GRID 128
#define PF 8
#define BSTRIDE 12                  // u32 words per batch in smem (10 used + pad)

typedef unsigned int u32;
typedef unsigned long long u64;

__device__ __forceinline__ void unpack2(u64 v, float& lo, float& hi) {
    asm("mov.b64 {%0,%1}, %2;" : "=f"(lo), "=f"(hi) : "l"(v));
}
__device__ __forceinline__ u32 cvt2h(float hi, float lo) {
    u32 d; asm("cvt.rn.f16x2.f32 %0, %1, %2;" : "=r"(d) : "f"(hi), "f"(lo)); return d;
}
__device__ __forceinline__ u32 hfma2(u32 a, u32 b, u32 c) {
    u32 d; asm("fma.rn.f16x2 %0, %1, %2, %3;" : "=r"(d) : "r"(a), "r"(b), "r"(c)); return d;
}
__device__ __forceinline__ u32 hadd2(u32 a, u32 b) {
    u32 d; asm("add.rn.f16x2 %0, %1, %2;" : "=r"(d) : "r"(a), "r"(b)); return d;
}
__device__ __forceinline__ u32 prmt(u32 a, u32 b, u32 sel) {
    u32 d; asm("prmt.b32 %0, %1, %2, %3;" : "=r"(d) : "r"(a), "r"(b), "r"(sel)); return d;
}
__device__ __forceinline__ u32 tanh2(u32 a) {
    u32 d; asm("tanh.approx.f16x2 %0, %1;" : "=r"(d) : "r"(a)); return d;
}

// One step for one lane (batch g, lane-role r, outputs 5r..5r+4).
__device__ __forceinline__ void rnn_step(
    const u32* __restrict__ src, u32* __restrict__ dst,
    int g, int r, ulonglong2 xv,
    const u32 Wp[5][10], const u32* __restrict__ Wi0, const u32* __restrict__ Wi1,
    const u32* __restrict__ seed)
{
    asm volatile("" ::: "memory");   // order previous stores before these loads
    const u32* hb = src + g * BSTRIDE;
    uint4 L0 = *reinterpret_cast<const uint4*>(hb);       // w0..w3
    uint4 L1 = *reinterpret_cast<const uint4*>(hb + 4);   // w4..w7
    uint2 L2 = *reinterpret_cast<const uint2*>(hb + 8);   // w8,w9

    // x projection (h-independent -> fills the LDS latency window)
    float x0, x1, x2, x3;
    unpack2(xv.x, x0, x1);
    unpack2(xv.y, x2, x3);
    u32 xh0 = cvt2h(x1, x0);
    u32 xh1 = cvt2h(x3, x2);

    u32 a[5], b[5];
    #pragma unroll
    for (int i = 0; i < 5; i++) {
        a[i] = hfma2(xh0, Wi0[i], seed[i]);
        a[i] = hfma2(xh1, Wi1[i], a[i]);
        b[i] = 0u;
    }
    #pragma unroll
    for (int i = 0; i < 5; i++) {
        a[i] = hfma2(L0.x, Wp[i][0], a[i]);  b[i] = hfma2(L0.y, Wp[i][1], b[i]);
        a[i] = hfma2(L0.z, Wp[i][2], a[i]);  b[i] = hfma2(L0.w, Wp[i][3], b[i]);
        a[i] = hfma2(L1.x, Wp[i][4], a[i]);  b[i] = hfma2(L1.y, Wp[i][5], b[i]);
        a[i] = hfma2(L1.z, Wp[i][6], a[i]);  b[i] = hfma2(L1.w, Wp[i][7], b[i]);
        a[i] = hfma2(L2.x, Wp[i][8], a[i]);  b[i] = hfma2(L2.y, Wp[i][9], b[i]);
    }

    u32 A0 = hadd2(a[0], b[0]);
    u32 A1 = hadd2(a[1], b[1]);
    u32 A2 = hadd2(a[2], b[2]);
    u32 A3 = hadd2(a[3], b[3]);
    u32 A4 = hadd2(a[4], b[4]);
    u32 E01 = hadd2(prmt(A0, A1, 0x5410), prmt(A0, A1, 0x7632)); // {pre0,pre1}
    u32 E23 = hadd2(prmt(A2, A3, 0x5410), prmt(A2, A3, 0x7632)); // {pre2,pre3}
    u32 E4  = hadd2(A4, prmt(A4, A4, 0x1032));                   // {pre4,pre4}
    u32 T01 = tanh2(E01);
    u32 T23 = tanh2(E23);
    u32 T4  = tanh2(E4);

    u32* ob = dst + g * BSTRIDE;
    *reinterpret_cast<uint2*>(ob + 2 * r) = make_uint2(T01, T23);    // w2r, w2r+1
    reinterpret_cast<__half*>(ob + 8)[r] =
        __ushort_as_half((unsigned short)(T4 & 0xffffu));            // extras half
}

__global__ void __launch_bounds__(CTA_THREADS, 1)
rnn_tanh_kernel(
    const float* __restrict__ x,     const float* __restrict__ h0,
    const float* __restrict__ W_ih,  const float* __restrict__ W_hh,
    const float* __restrict__ b_ih,  const float* __restrict__ b_hh,
    const float* __restrict__ fc_w,  const float* __restrict__ fc_b,
    float* __restrict__ out)
{
    __shared__ __align__(16) u32 sm[WARPS_CTA][2][8 * BSTRIDE + 4];

    const int lane = threadIdx.x & 31;
    const int w    = threadIdx.x >> 5;
    const int g    = lane >> 2;          // batch within warp (0..7)
    const int r    = lane & 3;           // lane role: outputs 5r..5r+4
    const int b    = (blockIdx.x * WARPS_CTA + w) * 8 + g;   // < 4096 exactly

    // word q of a batch holds h_{jlo[q]}, h_{jhi[q]}
    const int jlo[10] = {0, 2, 5, 7, 10, 12, 15, 17, 4, 14};
    const int jhi[10] = {1, 3, 6, 8, 11, 13, 16, 18, 9, 19};

    // ---- per-lane weights: 5 rows of W_hh packed in sigma order ----
    u32 Wp[5][10], Wi0[5], Wi1[5], seed[5];
    #pragma unroll
    for (int i = 0; i < 5; i++) {
        const int o = 5 * r + i;
        #pragma unroll
        for (int q = 0; q < 10; q++)
            Wp[i][q] = cvt2h(__ldg(&W_hh[o * H_DIM + jhi[q]]),
                             __ldg(&W_hh[o * H_DIM + jlo[q]]));
        Wi0[i] = cvt2h(__ldg(&W_ih[o * 4 + 1]), __ldg(&W_ih[o * 4 + 0]));
        Wi1[i] = cvt2h(__ldg(&W_ih[o * 4 + 3]), __ldg(&W_ih[o * 4 + 2]));
        seed[i] = cvt2h(0.f, __ldg(&b_ih[o]) + __ldg(&b_hh[o]));
    }

    u32* bufA = &sm[w][0][0];
    u32* bufB = &sm[w][1][0];

    // ---- init h into buffer A (same store pattern as the step) ----
    {
        float hv[5];
        #pragma unroll
        for (int i = 0; i < 5; i++) hv[i] = __ldg(&h0[b * H_DIM + 5 * r + i]);
        u32* ob = bufA + g * BSTRIDE;
        *reinterpret_cast<uint2*>(ob + 2 * r) =
            make_uint2(cvt2h(hv[1], hv[0]), cvt2h(hv[3], hv[2]));
        reinterpret_cast<__half*>(ob + 8)[r] = __float2half(hv[4]);
    }
    __syncwarp();

    // x[b][t] = 4 floats = one ulonglong2 (4 lanes broadcast). 8-deep ring.
    const ulonglong2* xp = reinterpret_cast<const ulonglong2*>(x) + (size_t)b * T_STEPS;
    ulonglong2 xbuf[PF];
    #pragma unroll
    for (int q = 0; q < PF; q++) xbuf[q] = __ldg(&xp[q]);

    for (int t = 0; t < T_STEPS - PF; t += PF) {
        #pragma unroll
        for (int q = 0; q < PF; q++) {
            ulonglong2 xv = xbuf[q];
            xbuf[q] = __ldg(&xp[t + q + PF]);
            if (q & 1) rnn_step(bufB, bufA, g, r, xv, Wp, Wi0, Wi1, seed);
            else       rnn_step(bufA, bufB, g, r, xv, Wp, Wi0, Wi1, seed);
        }
    }
    #pragma unroll
    for (int q = 0; q < PF; q++) {
        if (q & 1) rnn_step(bufB, bufA, g, r, xbuf[q], Wp, Wi0, Wi1, seed);
        else       rnn_step(bufA, bufB, g, r, xbuf[q], Wp, Wi0, Wi1, seed);
    }

    // Final h in bufA (T_STEPS even). Linear head: lane r -> out[b][r], all lanes live.
    __syncwarp();
    {
        const u32* hb = bufA + g * BSTRIDE;
        float acc = __ldg(&fc_b[r]);
        #pragma unroll
        for (int q = 0; q < 10; q++) {
            float2 hv = __half22float2(*reinterpret_cast<const __half2*>(&hb[q]));
            acc = fmaf(hv.x, __ldg(&fc_w[r * H_DIM + jlo[q]]), acc);
            acc = fmaf(hv.y, __ldg(&fc_w[r * H_DIM + jhi[q]]), acc);
        }
        out[b * 4 + r] = acc;
    }
}

extern "C" void kernel_launch(void* const* d_in, const int* in_sizes, int n_in,
                              void* d_out, int out_size)
{
    const float* x    = (const float*)d_in[0];
    const float* h0   = (const float*)d_in[1];
    const float* W_ih = (const float*)d_in[2];
    const float* W_hh = (const float*)d_in[3];
    const float* b_ih = (const float*)d_in[4];
    const float* b_hh = (const float*)d_in[5];
    const float* fc_w = (const float*)d_in[6];
    const float* fc_b = (const float*)d_in[7];
    float* out = (float*)d_out;

    rnn_tanh_kernel<<<GRID, CTA_THREADS>>>(x, h0, W_ih, W_hh, b_ih, b_hh,
                                           fc_w, fc_b, out);
}

// round 14
// speedup vs baseline: 1.0578x; 1.0578x over previous
#include <cuda_runtime.h>
#include <cuda_fp16.h>

// Vanilla tanh RNN: B=4096, T=2048, I=4, H=20, O=4.
// R14: 8 lanes/batch x 4 batches/warp (all 32 lanes live), 8 warps/CTA
// -> 1024 warps = 128 CTAs x exactly 2 warps/SMSP (mutual latency coverage),
// 128 SMs, 4096 = 128*8*4 exactly. Lanes 0-3 own 3 outputs {3r..3r+2},
// lanes 4-7 own 2 outputs {2r+4, 2r+5}; SIMT stream carries the 3-slot cost.
// h per batch = 10 fp16x2 words, pairing sigma:
//   w0..w3 = {0,1},{3,4},{6,7},{9,10}   (lanes 0-3 slots 0,1)
//   w4..w7 = {12,13},{14,15},{16,17},{18,19}  (lanes 4-7 slots 0,1)
//   w8 = {2,5}, w9 = {8,11}             (lanes 0-3 slot 2, half stores)
// W_hh packed at init in sigma order. Depth-6+6 a/b dot chains (fp16 error
// budget), tanh.approx.f16x2, warp-private SMEM ping-pong, syncwarp-free,
// 8-deep fp32 x register prefetch ring.

#define B_TOTAL 4096
#define T_STEPS 2048
#define H_DIM   20
#define WARPS_CTA 8
#define CTA_THREADS (WARPS_CTA * 32)
#define GRID 128
#define NB 4                        // batches per warp
#define PF 8
#define BSTRIDE 12                  // u32 words per batch in smem

typedef unsigned int u32;
typedef unsigned long long u64;

__device__ __forceinline__ void unpack2(u64 v, float& lo, float& hi) {
    asm("mov.b64 {%0,%1}, %2;" : "=f"(lo), "=f"(hi) : "l"(v));
}
__device__ __forceinline__ u32 cvt2h(float hi, float lo) {
    u32 d; asm("cvt.rn.f16x2.f32 %0, %1, %2;" : "=r"(d) : "f"(hi), "f"(lo)); return d;
}
__device__ __forceinline__ u32 hfma2(u32 a, u32 b, u32 c) {
    u32 d; asm("fma.rn.f16x2 %0, %1, %2, %3;" : "=r"(d) : "r"(a), "r"(b), "r"(c)); return d;
}
__device__ __forceinline__ u32 hadd2(u32 a, u32 b) {
    u32 d; asm("add.rn.f16x2 %0, %1, %2;" : "=r"(d) : "r"(a), "r"(b)); return d;
}
__device__ __forceinline__ u32 prmt(u32 a, u32 b, u32 sel) {
    u32 d; asm("prmt.b32 %0, %1, %2, %3;" : "=r"(d) : "r"(a), "r"(b), "r"(sel)); return d;
}
__device__ __forceinline__ u32 tanh2(u32 a) {
    u32 d; asm("tanh.approx.f16x2 %0, %1;" : "=r"(d) : "r"(a)); return d;
}

// One step for one lane (batch-group g, lane-role r).
__device__ __forceinline__ void rnn_step(
    const u32* __restrict__ src, u32* __restrict__ dst,
    int g, int r, bool hstore, ulonglong2 xv,
    const u32 Wa[3][6], const u32 Wb[3][5], const u32* __restrict__ seed)
{
    asm volatile("" ::: "memory");   // order previous stores before these loads
    const u32* hb = src + g * BSTRIDE;
    uint4 L0 = *reinterpret_cast<const uint4*>(hb);       // w0..w3
    uint4 L1 = *reinterpret_cast<const uint4*>(hb + 4);   // w4..w7
    uint2 L2 = *reinterpret_cast<const uint2*>(hb + 8);   // w8,w9

    float x0, x1, x2, x3;
    unpack2(xv.x, x0, x1);
    unpack2(xv.y, x2, x3);
    u32 xh0 = cvt2h(x1, x0);
    u32 xh1 = cvt2h(x3, x2);

    u32 A[3];
    #pragma unroll
    for (int i = 0; i < 3; i++) {
        // a-chain: bias + x proj + words 0..4   (Wa[i][0..1] are W_ih pairs)
        u32 a = hfma2(xh0, Wa[i][0], seed[i]);
        a = hfma2(xh1, Wa[i][1], a);
        a = hfma2(L0.x, Wa[i][2], a);
        a = hfma2(L0.y, Wa[i][3], a);
        a = hfma2(L0.z, Wa[i][4], a);
        a = hfma2(L0.w, Wa[i][5], a);
        // b-chain: words 4..9
        u32 b = hfma2(L1.x, Wb[i][0], 0u);
        b = hfma2(L1.y, Wb[i][1], b);
        b = hfma2(L1.z, Wb[i][2], b);
        b = hfma2(L1.w, Wb[i][3], b);
        b = hfma2(L2.x, Wb[i][4], b);
        // w9 folded into a to keep depth 6/6
        a = hfma2(L2.y, Wa[i][2 + 4] /*unused slot? no*/, a);
        A[i] = hadd2(a, b);
    }
    // NOTE: the line above is replaced below -- see W layout (Wa has 6, Wb 5, w9 via Wb).
    (void)A;
}

// ---- The step above is illustrative; real implementation below (W split 7/5). ----

__device__ __forceinline__ void rnn_step_real(
    const u32* __restrict__ src, u32* __restrict__ dst,
    int g, int r, bool hstore, ulonglong2 xv,
    const u32 Wa[3][7], const u32 Wb[3][5], const u32* __restrict__ seed)
{
    asm volatile("" ::: "memory");
    const u32* hb = src + g * BSTRIDE;
    uint4 L0 = *reinterpret_cast<const uint4*>(hb);       // w0..w3
    uint4 L1 = *reinterpret_cast<const uint4*>(hb + 4);   // w4..w7
    uint2 L2 = *reinterpret_cast<const uint2*>(hb + 8);   // w8,w9

    float x0, x1, x2, x3;
    unpack2(xv.x, x0, x1);
    unpack2(xv.y, x2, x3);
    u32 xh0 = cvt2h(x1, x0);
    u32 xh1 = cvt2h(x3, x2);

    u32 A[3];
    #pragma unroll
    for (int i = 0; i < 3; i++) {
        // a-chain (depth 7): bias, 2 proj, words 0..3, word 8
        u32 a = hfma2(xh0, Wa[i][0], seed[i]);
        a = hfma2(xh1,  Wa[i][1], a);
        a = hfma2(L0.x, Wa[i][2], a);
        a = hfma2(L0.y, Wa[i][3], a);
        a = hfma2(L0.z, Wa[i][4], a);
        a = hfma2(L0.w, Wa[i][5], a);
        a = hfma2(L2.x, Wa[i][6], a);
        // b-chain (depth 5): words 4..7, word 9
        u32 b = hfma2(L1.x, Wb[i][0], 0u);
        b = hfma2(L1.y, Wb[i][1], b);
        b = hfma2(L1.z, Wb[i][2], b);
        b = hfma2(L1.w, Wb[i][3], b);
        b = hfma2(L2.y, Wb[i][4], b);
        A[i] = hadd2(a, b);
    }

    // word {pre0, pre1} and half pre2
    u32 E01 = hadd2(prmt(A[0], A[1], 0x5410), prmt(A[0], A[1], 0x7632));
    u32 T01 = tanh2(E01);
    u32 E2  = hadd2(A[2], prmt(A[2], A[2], 0x1032));
    u32 T2  = tanh2(E2);

    u32* ob = dst + g * BSTRIDE;
    ob[r] = T01;                                   // words w0..w7 by lane role
    if (hstore)                                    // lanes 0-3: slot-2 half
        reinterpret_cast<__half*>(ob + 8)[r] =
            __ushort_as_half((unsigned short)(T2 & 0xffffu));
}

__global__ void __launch_bounds__(CTA_THREADS, 1)
rnn_tanh_kernel(
    const float* __restrict__ x,     const float* __restrict__ h0,
    const float* __restrict__ W_ih,  const float* __restrict__ W_hh,
    const float* __restrict__ b_ih,  const float* __restrict__ b_hh,
    const float* __restrict__ fc_w,  const float* __restrict__ fc_b,
    float* __restrict__ out)
{
    __shared__ __align__(16) u32 sm[WARPS_CTA][2][NB * BSTRIDE];

    const int lane = threadIdx.x & 31;
    const int w    = threadIdx.x >> 5;
    const int g    = lane >> 3;                  // batch within warp (0..3)
    const int r    = lane & 7;                   // lane role
    const int b    = (blockIdx.x * WARPS_CTA + w) * NB + g;   // < 4096 exactly
    const bool hstore = (r < 4);

    // sigma: word q holds {h_jlo[q], h_jhi[q]}
    const int jlo[10] = {0, 3, 6, 9, 12, 14, 16, 18, 2, 8};
    const int jhi[10] = {1, 4, 7, 10, 13, 15, 17, 19, 5, 11};

    // lane's outputs
    const int o0 = hstore ? (3 * r)     : (2 * r + 4);
    const int o1 = hstore ? (3 * r + 1) : (2 * r + 5);
    const int o2 = hstore ? (3 * r + 2) : (2 * r + 5);   // dummy for r>=4

    // ---- per-lane weights: Wa (proj pair + words 0..3 + word 8), Wb (words 4..7 + 9) ----
    u32 Wa[3][7], Wb[3][5], seed[3];
    const int oo[3] = {o0, o1, o2};
    #pragma unroll
    for (int i = 0; i < 3; i++) {
        const int o = oo[i];
        Wa[i][0] = cvt2h(__ldg(&W_ih[o * 4 + 1]), __ldg(&W_ih[o * 4 + 0]));
        Wa[i][1] = cvt2h(__ldg(&W_ih[o * 4 + 3]), __ldg(&W_ih[o * 4 + 2]));
        #pragma unroll
        for (int q = 0; q < 4; q++)
            Wa[i][2 + q] = cvt2h(__ldg(&W_hh[o * H_DIM + jhi[q]]),
                                 __ldg(&W_hh[o * H_DIM + jlo[q]]));
        Wa[i][6] = cvt2h(__ldg(&W_hh[o * H_DIM + jhi[8]]),
                         __ldg(&W_hh[o * H_DIM + jlo[8]]));
        #pragma unroll
        for (int q = 0; q < 4; q++)
            Wb[i][q] = cvt2h(__ldg(&W_hh[o * H_DIM + jhi[4 + q]]),
                             __ldg(&W_hh[o * H_DIM + jlo[4 + q]]));
        Wb[i][4] = cvt2h(__ldg(&W_hh[o * H_DIM + jhi[9]]),
                         __ldg(&W_hh[o * H_DIM + jlo[9]]));
        seed[i] = cvt2h(0.f, __ldg(&b_ih[o]) + __ldg(&b_hh[o]));
    }

    u32* bufA = &sm[w][0][0];
    u32* bufB = &sm[w][1][0];

    // ---- init h into buffer A (same pattern as the step) ----
    {
        u32* ob = bufA + g * BSTRIDE;
        ob[r] = cvt2h(__ldg(&h0[b * H_DIM + o1]), __ldg(&h0[b * H_DIM + o0]));
        if (hstore)
            reinterpret_cast<__half*>(ob + 8)[r] = __float2half(__ldg(&h0[b * H_DIM + o2]));
    }
    __syncwarp();

    // x ring (all 8 lanes of a group broadcast-load the same 16B)
    const ulonglong2* xp = reinterpret_cast<const ulonglong2*>(x) + (size_t)b * T_STEPS;
    ulonglong2 xbuf[PF];
    #pragma unroll
    for (int q = 0; q < PF; q++) xbuf[q] = __ldg(&xp[q]);

    for (int t = 0; t < T_STEPS - PF; t += PF) {
        #pragma unroll
        for (int q = 0; q < PF; q++) {
            ulonglong2 xv = xbuf[q];
            xbuf[q] = __ldg(&xp[t + q + PF]);
            if (q & 1) rnn_step_real(bufB, bufA, g, r, hstore, xv, Wa, Wb, seed);
            else       rnn_step_real(bufA, bufB, g, r, hstore, xv, Wa, Wb, seed);
        }
    }
    #pragma unroll
    for (int q = 0; q < PF; q++) {
        if (q & 1) rnn_step_real(bufB, bufA, g, r, hstore, xbuf[q], Wa, Wb, seed);
        else       rnn_step_real(bufA, bufB, g, r, hstore, xbuf[q], Wa, Wb, seed);
    }

    // Final h in bufA. Head: lanes r<4 of each group -> out[b][r].
    __syncwarp();
    if (hstore) {
        const u32* hb = bufA + g * BSTRIDE;
        float acc = __ldg(&fc_b[r]);
        #pragma unroll
        for (int q = 0; q < 10; q++) {
            float2 hv = __half22float2(*reinterpret_cast<const __half2*>(&hb[q]));
            acc = fmaf(hv.x, __ldg(&fc_w[r * H_DIM + jlo[q]]), acc);
            acc = fmaf(hv.y, __ldg(&fc_w[r * H_DIM + jhi[q]]), acc);
        }
        out[b * 4 + r] = acc;
    }
}

extern "C" void kernel_launch(void* const* d_in, const int* in_sizes, int n_in,
                              void* d_out, int out_size)
{
    const float* x    = (const float*)d_in[0];
    const float* h0   = (const float*)d_in[1];
    const float* W_ih = (const float*)d_in[2];
    const float* W_hh = (const float*)d_in[3];
    const float* b_ih = (const float*)d_in[4];
    const float* b_hh = (const float*)d_in[5];
    const float* fc_w = (const float*)d_in[6];
    const float* fc_b = (const float*)d_in[7];
    float* out = (float*)d_out;

    rnn_tanh_kernel<<<GRID, CTA_THREADS>>>(x, h0, W_ih, W_hh, b_ih, b_hh,
                                           fc_w, fc_b, out);
}

// round 15
// speedup vs baseline: 1.1026x; 1.0423x over previous
#include <cuda_runtime.h>
#include <cuda_fp16.h>

// Vanilla tanh RNN: B=4096, T=2048, I=4, H=20, O=4.
// R15 = R12 (best shell: fp16x2/HFMA2 recurrence, 10 warps/CTA, 3 batches/warp,
// 30/32 lanes live, warp-private SMEM ping-pong, syncwarp-free, tanh.approx.f16x2)
// with trims: x prefetch ring pre-converted to fp16x2 (uint2/entry -> fewer regs,
// fewer per-step MOVs, less RF bank pressure); stagger block removed (measured ~0);
// true depth-6/6 a/b dot chains.

#define B_TOTAL 4096
#define T_STEPS 2048
#define H_DIM   20
#define O_DIM   4
#define WARPS_CTA 10
#define CTA_THREADS (WARPS_CTA * 32)
#define GRID 148
#define PF 8                        // x prefetch depth (steps)
#define HSTRIDE 12                  // u32 stride per batch in smem

typedef unsigned int u32;
typedef unsigned long long u64;

__device__ __forceinline__ void unpack2(u64 v, float& lo, float& hi) {
    asm("mov.b64 {%0,%1}, %2;" : "=f"(lo), "=f"(hi) : "l"(v));
}
__device__ __forceinline__ u32 cvt2h(float hi, float lo) {
    u32 d; asm("cvt.rn.f16x2.f32 %0, %1, %2;" : "=r"(d) : "f"(hi), "f"(lo)); return d;
}
__device__ __forceinline__ u32 hfma2(u32 a, u32 b, u32 c) {
    u32 d; asm("fma.rn.f16x2 %0, %1, %2, %3;" : "=r"(d) : "r"(a), "r"(b), "r"(c)); return d;
}
__device__ __forceinline__ u32 hadd2(u32 a, u32 b) {
    u32 d; asm("add.rn.f16x2 %0, %1, %2;" : "=r"(d) : "r"(a), "r"(b)); return d;
}
__device__ __forceinline__ u32 prmt(u32 a, u32 b, u32 sel) {
    u32 d; asm("prmt.b32 %0, %1, %2, %3;" : "=r"(d) : "r"(a), "r"(b), "r"(sel)); return d;
}
__device__ __forceinline__ u32 tanh2(u32 a) {
    u32 d; asm("tanh.approx.f16x2 %0, %1;" : "=r"(d) : "r"(a)); return d;
}

// Load x[t] (4 fp32) and convert to two fp16x2 words.
__device__ __forceinline__ uint2 xld(const ulonglong2* __restrict__ p) {
    ulonglong2 v = __ldg(p);
    float x0, x1, x2, x3;
    unpack2(v.x, x0, x1);
    unpack2(v.y, x2, x3);
    return make_uint2(cvt2h(x1, x0), cvt2h(x3, x2));
}

// One RNN step (batch g, outputs o0=2p, o0+1). Branch-free; unconditional store.
__device__ __forceinline__ void rnn_step(
    const u32* __restrict__ src, u32* __restrict__ dst,
    int g, int sOff, uint2 xh,
    const u32* __restrict__ W0, const u32* __restrict__ W1,
    u32 Wi0a, u32 Wi0b, u32 Wi1a, u32 Wi1b, u32 seed0, u32 seed1)
{
    asm volatile("" ::: "memory");  // order prior STS before this step's LDS
    const u32* hb = src + g * HSTRIDE;
    uint4 hA = *reinterpret_cast<const uint4*>(hb);       // w0..w3
    uint4 hB = *reinterpret_cast<const uint4*>(hb + 4);   // w4..w7
    uint2 hC = *reinterpret_cast<const uint2*>(hb + 8);   // w8,w9

    // Depth-6/6 chains per output: a = [seed + xh0] + w0..w4, b = [xh1] + w5..w9.
    u32 a0 = hfma2(xh.x, Wi0a, seed0);
    u32 b0 = hfma2(xh.y, Wi0b, 0u);
    u32 a1 = hfma2(xh.x, Wi1a, seed1);
    u32 b1 = hfma2(xh.y, Wi1b, 0u);

    a0 = hfma2(hA.x, W0[0], a0);  b0 = hfma2(hB.y, W0[5], b0);
    a1 = hfma2(hA.x, W1[0], a1);  b1 = hfma2(hB.y, W1[5], b1);
    a0 = hfma2(hA.y, W0[1], a0);  b0 = hfma2(hB.z, W0[6], b0);
    a1 = hfma2(hA.y, W1[1], a1);  b1 = hfma2(hB.z, W1[6], b1);
    a0 = hfma2(hA.z, W0[2], a0);  b0 = hfma2(hB.w, W0[7], b0);
    a1 = hfma2(hA.z, W1[2], a1);  b1 = hfma2(hB.w, W1[7], b1);
    a0 = hfma2(hA.w, W0[3], a0);  b0 = hfma2(hC.x, W0[8], b0);
    a1 = hfma2(hA.w, W1[3], a1);  b1 = hfma2(hC.x, W1[8], b1);
    a0 = hfma2(hB.x, W0[4], a0);  b0 = hfma2(hC.y, W0[9], b0);
    a1 = hfma2(hB.x, W1[4], a1);  b1 = hfma2(hC.y, W1[9], b1);

    u32 A = hadd2(a0, b0);          // {p, q}
    u32 B = hadd2(a1, b1);          // {r, s}
    u32 C = prmt(A, B, 0x5410);     // {p, r}
    u32 D = prmt(A, B, 0x7632);     // {q, s}
    u32 E = hadd2(C, D);            // {o0pre, o1pre}
    u32 hn = tanh2(E);

    dst[sOff] = hn;                 // unconditional STS.32
}

__global__ void __launch_bounds__(CTA_THREADS, 1)
rnn_tanh_kernel(
    const float* __restrict__ x,     const float* __restrict__ h0,
    const float* __restrict__ W_ih,  const float* __restrict__ W_hh,
    const float* __restrict__ b_ih,  const float* __restrict__ b_hh,
    const float* __restrict__ fc_w,  const float* __restrict__ fc_b,
    float* __restrict__ out)
{
    __shared__ __align__(16) u32 sm[WARPS_CTA][2][40];

    const int lane = threadIdx.x & 31;
    const int w    = threadIdx.x >> 5;
    const int gw   = blockIdx.x * WARPS_CTA + w;
    if (gw * 3 >= B_TOTAL) return;

    const bool live = (lane < 30);
    const int  g    = live ? (lane / 10) : 2;
    const int  p    = live ? (lane % 10) : (lane - 30);
    const int  b    = gw * 3 + g;
    const int  bc   = (b < B_TOTAL) ? b : (B_TOTAL - 1);
    const int  o0   = 2 * p;
    const int  sOff = live ? (g * HSTRIDE + p) : (38 + (lane - 30));

    // ---- per-thread weights: fp16x2 packed over j ----
    u32 W0[10], W1[10];
    #pragma unroll
    for (int q = 0; q < 10; q++) {
        W0[q] = cvt2h(__ldg(&W_hh[o0 * H_DIM + 2 * q + 1]),
                      __ldg(&W_hh[o0 * H_DIM + 2 * q]));
        W1[q] = cvt2h(__ldg(&W_hh[(o0 + 1) * H_DIM + 2 * q + 1]),
                      __ldg(&W_hh[(o0 + 1) * H_DIM + 2 * q]));
    }
    const u32 Wi0a = cvt2h(__ldg(&W_ih[o0 * 4 + 1]), __ldg(&W_ih[o0 * 4 + 0]));
    const u32 Wi0b = cvt2h(__ldg(&W_ih[o0 * 4 + 3]), __ldg(&W_ih[o0 * 4 + 2]));
    const u32 Wi1a = cvt2h(__ldg(&W_ih[(o0 + 1) * 4 + 1]), __ldg(&W_ih[(o0 + 1) * 4 + 0]));
    const u32 Wi1b = cvt2h(__ldg(&W_ih[(o0 + 1) * 4 + 3]), __ldg(&W_ih[(o0 + 1) * 4 + 2]));
    const u32 seed0 = cvt2h(0.f, __ldg(&b_ih[o0])     + __ldg(&b_hh[o0]));
    const u32 seed1 = cvt2h(0.f, __ldg(&b_ih[o0 + 1]) + __ldg(&b_hh[o0 + 1]));

    u32* bufA = &sm[w][0][0];
    u32* bufB = &sm[w][1][0];

    // ---- init h (fp16x2) into buffer A ----
    {
        const float2* h2 = reinterpret_cast<const float2*>(h0);
        float2 hv = __ldg(&h2[bc * (H_DIM / 2) + p]);
        bufA[sOff] = cvt2h(hv.y, hv.x);
    }
    __syncwarp();

    // x ring: fp16x2-converted at prefetch time (uint2 per step entry).
    const ulonglong2* xp = reinterpret_cast<const ulonglong2*>(x) + (size_t)bc * T_STEPS;
    uint2 xbuf[PF];
    #pragma unroll
    for (int q = 0; q < PF; q++) xbuf[q] = xld(&xp[q]);

    for (int t = 0; t < T_STEPS - PF; t += PF) {
        #pragma unroll
        for (int q = 0; q < PF; q++) {
            uint2 xh = xbuf[q];
            xbuf[q] = xld(&xp[t + q + PF]);
            if (q & 1)
                rnn_step(bufB, bufA, g, sOff, xh, W0, W1, Wi0a, Wi0b, Wi1a, Wi1b, seed0, seed1);
            else
                rnn_step(bufA, bufB, g, sOff, xh, W0, W1, Wi0a, Wi0b, Wi1a, Wi1b, seed0, seed1);
        }
    }
    #pragma unroll
    for (int q = 0; q < PF; q++) {
        if (q & 1)
            rnn_step(bufB, bufA, g, sOff, xbuf[q], W0, W1, Wi0a, Wi0b, Wi1a, Wi1b, seed0, seed1);
        else
            rnn_step(bufA, bufB, g, sOff, xbuf[q], W0, W1, Wi0a, Wi0b, Wi1a, Wi1b, seed0, seed1);
    }

    // Final h in bufA (T_STEPS even). Linear head in fp32 from fp16 h.
    __syncwarp();
    if (live && p < O_DIM && b < B_TOTAL) {
        const u32* hb = bufA + g * HSTRIDE;
        float acc = __ldg(&fc_b[p]);
        #pragma unroll
        for (int q = 0; q < 10; q++) {
            float2 hv = __half22float2(*reinterpret_cast<const __half2*>(&hb[q]));
            acc = fmaf(hv.x, __ldg(&fc_w[p * H_DIM + 2 * q]),     acc);
            acc = fmaf(hv.y, __ldg(&fc_w[p * H_DIM + 2 * q + 1]), acc);
        }
        out[b * O_DIM + p] = acc;
    }
}

extern "C" void kernel_launch(void* const* d_in, const int* in_sizes, int n_in,
                              void* d_out, int out_size)
{
    const float* x    = (const float*)d_in[0];
    const float* h0   = (const float*)d_in[1];
    const float* W_ih = (const float*)d_in[2];
    const float* W_hh = (const float*)d_in[3];
    const float* b_ih = (const float*)d_in[4];
    const float* b_hh = (const float*)d_in[5];
    const float* fc_w = (const float*)d_in[6];
    const float* fc_b = (const float*)d_in[7];
    float* out = (float*)d_out;

    rnn_tanh_kernel<<<GRID, CTA_THREADS>>>(x, h0, W_ih, W_hh, b_ih, b_hh,
                                           fc_w, fc_b, out);
}